// round 12
// baseline (speedup 1.0000x reference)
#include <cuda_runtime.h>
#include <cuda_fp16.h>
#include <cstdint>
#include <cstddef>

#define FMAXD 1024
#define GMAX  256
#define MAXN  40960

// ---------------- scratch (static device globals; no runtime allocation) ---
__device__ float  g_feat[(size_t)MAXN * FMAXD];
__device__ __half g_Yh[(size_t)MAXN * FMAXD];
__device__ __half g_Wh[(size_t)FMAXD * FMAXD];
__device__ float  g_sum[GMAX * FMAXD];
__device__ float  g_sq[GMAX * FMAXD];
__device__ float  g_s[GMAX * FMAXD];
__device__ float  g_t[GMAX * FMAXD];
__device__ int    g_cnt[GMAX];

// ---------------- helpers ---------------------------------------------------
__device__ __forceinline__ void cp16(uint32_t dst, const void* src) {
    asm volatile("cp.async.cg.shared.global [%0], [%1], 16;\n" :: "r"(dst), "l"(src));
}
__device__ __forceinline__ void cp_commit() { asm volatile("cp.async.commit_group;\n"); }
template <int n> __device__ __forceinline__ void cp_wait() {
    asm volatile("cp.async.wait_group %0;\n" :: "n"(n));
}
__device__ __forceinline__ void l2_prefetch(const void* p) {
    asm volatile("prefetch.global.L2 [%0];" :: "l"(p));
}

// ---------------- small kernels ---------------------------------------------
// Fused: zero sums + histogram node counts (one launch).
__global__ void init_stats(const int* __restrict__ seg, int N) {
    int i = blockIdx.x * blockDim.x + threadIdx.x;
    if (i < GMAX * FMAXD) { g_sum[i] = 0.f; g_sq[i] = 0.f; }
    if (i < GMAX) g_cnt[i] = 0;
    // histogram after a grid-wide dependency? g_cnt zeroing and atomics from
    // different blocks can interleave — instead compute counts privately:
    // every block histograms its slice into smem, then adds AFTER the zeroing
    // of g_cnt is guaranteed... not guaranteed across blocks. So: compute
    // counts non-atomically via a dedicated range below (block 0 only, after
    // its own zero of g_cnt — safe because ONLY block 0 touches g_cnt).
    if (blockIdx.x == 0) {
        __shared__ int h[GMAX];
        for (int k = threadIdx.x; k < GMAX; k += blockDim.x) h[k] = 0;
        __syncthreads();
        for (int n = threadIdx.x; n < N; n += blockDim.x) atomicAdd(&h[seg[n]], 1);
        __syncthreads();
        for (int k = threadIdx.x; k < GMAX; k += blockDim.x) g_cnt[k] = h[k];
    }
}

// Pass 1 (vectorized): each thread owns a feature-quad.
__global__ void pass1(const float* __restrict__ fv, const int* __restrict__ seg,
                      int N, int F, int npb) {
    int q  = blockIdx.x * blockDim.x + threadIdx.x;   // feature quad
    if (q >= F / 4) return;
    int n0 = blockIdx.y * npb;
    if (n0 >= N) return;
    int nend = min(n0 + npb, N);
    float s1[4] = {0.f, 0.f, 0.f, 0.f};
    float s2[4] = {0.f, 0.f, 0.f, 0.f};
    int curg = seg[n0];
    int f0 = 4 * q;
    for (int n = n0; n < nend; ++n) {
        int g = seg[n];
        if (g != curg) {
#pragma unroll
            for (int k = 0; k < 4; ++k) {
                atomicAdd(&g_sum[curg * F + f0 + k], s1[k]);
                atomicAdd(&g_sq[curg * F + f0 + k], s2[k]);
                s1[k] = 0.f; s2[k] = 0.f;
            }
            curg = g;
        }
        const float4* p = reinterpret_cast<const float4*>(fv + ((size_t)n * F + f0) * 3);
        float4 a = p[0], b = p[1], c = p[2];
        float x0 = a.x + 1e-8f, y0 = a.y + 1e-8f, z0 = a.z + 1e-8f;
        float x1 = a.w + 1e-8f, y1 = b.x + 1e-8f, z1 = b.y + 1e-8f;
        float x2 = b.z + 1e-8f, y2 = b.w + 1e-8f, z2 = c.x + 1e-8f;
        float x3 = c.y + 1e-8f, y3 = c.z + 1e-8f, z3 = c.w + 1e-8f;
        float4 ft;
        ft.x = sqrtf(fmaf(x0, x0, fmaf(y0, y0, z0 * z0)));
        ft.y = sqrtf(fmaf(x1, x1, fmaf(y1, y1, z1 * z1)));
        ft.z = sqrtf(fmaf(x2, x2, fmaf(y2, y2, z2 * z2)));
        ft.w = sqrtf(fmaf(x3, x3, fmaf(y3, y3, z3 * z3)));
        reinterpret_cast<float4*>(g_feat + (size_t)n * F + f0)[0] = ft;
        s1[0] += ft.x; s2[0] = fmaf(ft.x, ft.x, s2[0]);
        s1[1] += ft.y; s2[1] = fmaf(ft.y, ft.y, s2[1]);
        s1[2] += ft.z; s2[2] = fmaf(ft.z, ft.z, s2[2]);
        s1[3] += ft.w; s2[3] = fmaf(ft.w, ft.w, s2[3]);
    }
#pragma unroll
    for (int k = 0; k < 4; ++k) {
        atomicAdd(&g_sum[curg * F + f0 + k], s1[k]);
        atomicAdd(&g_sq[curg * F + f0 + k], s2[k]);
    }
}

// Per-(g,f) affine coefficients: y = feat*s + t
__global__ void stats(const float* __restrict__ alpha, const float* __restrict__ beta,
                      const float* __restrict__ gamma, int F) {
    int f = blockIdx.x * blockDim.x + threadIdx.x;
    int g = blockIdx.y;
    int c = g_cnt[g];
    if (c == 0) return;
    float invc = 1.f / (float)c;
    size_t idx = (size_t)g * F + f;
    float u  = g_sum[idx] * invc;
    float u2 = alpha[f] * u;
    float m2 = g_sq[idx] * invc;
    float sigma = m2 - 2.f * u2 * u + u2 * u2;
    float sn = sqrtf(sigma + 1e-6f);
    float iv = 1.f / (sn + 1e-6f);
    float sv = gamma[f] * iv;
    g_s[idx] = sv;
    g_t[idx] = fmaf(-u2, sv, beta[f]);
}

// Y = feat*s + t, cast to fp16
__global__ void make_y(const int* __restrict__ seg, int N, int F) {
    int q = F / 4;
    long long i = (long long)blockIdx.x * blockDim.x + threadIdx.x;
    if (i >= (long long)N * q) return;
    int n = (int)(i / q);
    int j = (int)(i % q);
    int g = seg[n];
    float4 ft = reinterpret_cast<const float4*>(g_feat)[(size_t)n * q + j];
    float4 sv = reinterpret_cast<const float4*>(g_s)[(size_t)g * q + j];
    float4 tv = reinterpret_cast<const float4*>(g_t)[(size_t)g * q + j];
    __half2 y01, y23;
    y01.x = __float2half(fmaf(ft.x, sv.x, tv.x));
    y01.y = __float2half(fmaf(ft.y, sv.y, tv.y));
    y23.x = __float2half(fmaf(ft.z, sv.z, tv.z));
    y23.y = __float2half(fmaf(ft.w, sv.w, tv.w));
    __half2* dst = reinterpret_cast<__half2*>(g_Yh + (size_t)n * F + 4 * j);
    dst[0] = y01; dst[1] = y23;
}

__global__ void conv_w(const float* __restrict__ W, int total4) {
    int i = blockIdx.x * blockDim.x + threadIdx.x;
    if (i >= total4) return;
    float4 w = reinterpret_cast<const float4*>(W)[i];
    __half2 h01, h23;
    h01.x = __float2half(w.x); h01.y = __float2half(w.y);
    h23.x = __float2half(w.z); h23.y = __float2half(w.w);
    __half2* dst = reinterpret_cast<__half2*>(g_Wh + (size_t)4 * i);
    dst[0] = h01; dst[1] = h23;
}

// ---------------- fp16 mma.sync GEMM with fused final rescale epilogue ------
// BM=128, BN=128, 256 thr, warp tile 64x32, NSTAGE=3 -> smem 110.6KB -> occ 2.
// Y (64MB) and W (2MB) stay L2-resident across transit; occ-2 overlaps one
// CTA's epilogue (DRAM-heavy) with the co-resident CTA's mainloop (tensor).
#define BM 128
#define BN 128
#define BK 64
#define RSTR 72                          // 64 data + 8 pad halfs (144B rows)
#define A_STG (BM * RSTR)
#define B_STG (BN * RSTR)
#define NSTAGE 3
#define SMEM_B ((NSTAGE * (A_STG + B_STG)) * 2)   // 110592 bytes
#define NTHR 256

__global__ void __launch_bounds__(NTHR, 2) gemm_fused(
    const float* __restrict__ fv, const float* __restrict__ zeta,
    const float* __restrict__ bias, float* __restrict__ out, int N, int F) {
    extern __shared__ __half sm[];
    __half* As = sm;                        // [NSTAGE][BM][RSTR]
    __half* Bs = sm + NSTAGE * A_STG;       // [NSTAGE][BN][RSTR]
    int tid = threadIdx.x;
    int m0 = blockIdx.y * BM;
    int n0 = blockIdx.x * BN;
    uint32_t asBase = (uint32_t)__cvta_generic_to_shared(As);
    uint32_t bsBase = (uint32_t)__cvta_generic_to_shared(Bs);
    int NK = F / BK;                        // 16

    float acc[4][4][4];
#pragma unroll
    for (int a = 0; a < 4; ++a)
#pragma unroll
        for (int b = 0; b < 4; ++b)
#pragma unroll
            for (int c2 = 0; c2 < 4; ++c2) acc[a][b][c2] = 0.f;

    int wid = tid / 32, lane = tid % 32;
    int warpM = (wid >> 2) * 64;            // 2 warp rows (64 m each)
    int warpN = (wid & 3) * 32;             // 4 warp cols (32 n each)
    int r = lane >> 2, c = lane & 3;

    auto loadAB = [&](int st, int kt) {
#pragma unroll
        for (int it = 0; it < 4; ++it) {    // A: 1024 chunks / 256 thr
            int id = tid + NTHR * it;
            int row = id >> 3, ch = id & 7;
            int gr = m0 + row; if (gr > N - 1) gr = N - 1;
            const void* srcA = g_Yh + (size_t)gr * F + kt * BK + ch * 8;
            cp16(asBase + (uint32_t)(st * A_STG + row * RSTR) * 2u + ch * 16u, srcA);
        }
#pragma unroll
        for (int it = 0; it < 4; ++it) {    // B: 1024 chunks / 256 thr
            int id = tid + NTHR * it;
            int row = id >> 3, ch = id & 7;
            const void* srcB = g_Wh + (size_t)(n0 + row) * F + kt * BK + ch * 8;
            cp16(bsBase + (uint32_t)(st * B_STG + row * RSTR) * 2u + ch * 16u, srcB);
        }
    };

    // Prologue: NSTAGE-1 = 2 stages
    loadAB(0, 0); cp_commit();
    loadAB(1, 1); cp_commit();

    int l8 = lane & 7, lg = lane >> 3;      // ldmatrix lane grouping

    for (int kt = 0; kt < NK; ++kt) {
        int st = kt % NSTAGE;
        // committed = 2 + kt before this wait; wait_group 1 => tiles 0..kt done.
        cp_wait<1>();
        __syncthreads();
        // Issue tile kt+2 into stage (kt+2)%3 = (kt-1)%3, consumed last
        // iteration; all warps are past it once past this barrier. 1 sync/kt.
        {
            int kn = kt + NSTAGE - 1;
            if (kn < NK) loadAB(kn % NSTAGE, kn);
            cp_commit();                     // always commit (empty in tail)
        }
        if (kt == 4) {
            // L2-prefetch epilogue fv footprint: 128 rows x 128 feats x 12B
            // = 1536 lines of 128B; 6 per thread.
#pragma unroll
            for (int i = 0; i < 6; ++i) {
                int id = tid + NTHR * i;     // 0..1535
                int row = id / 12, sl = id % 12;
                int gr = m0 + row; if (gr > N - 1) gr = N - 1;
                const char* p = reinterpret_cast<const char*>(
                    fv + ((size_t)gr * F + n0) * 3) + sl * 128;
                l2_prefetch(p);
            }
        }
        const __half* At = As + st * A_STG;
        const __half* Bt = Bs + st * B_STG;
#pragma unroll
        for (int ks = 0; ks < 4; ++ks) {    // 4 k16-steps per BK=64
            uint32_t a[4][4], bb[4][2];
#pragma unroll
            for (int mt = 0; mt < 4; ++mt) {
                int arow = warpM + mt * 16 + ((lg & 1) ? 8 : 0) + l8;
                int acol = ks * 16 + ((lg >> 1) ? 8 : 0);
                uint32_t addr = (uint32_t)__cvta_generic_to_shared(At + arow * RSTR + acol);
                asm volatile("ldmatrix.sync.aligned.m8n8.x4.shared.b16 {%0,%1,%2,%3}, [%4];"
                             : "=r"(a[mt][0]), "=r"(a[mt][1]), "=r"(a[mt][2]), "=r"(a[mt][3])
                             : "r"(addr));
            }
#pragma unroll
            for (int pp = 0; pp < 2; ++pp) {
                int brow = warpN + pp * 16 + ((lg >> 1) ? 8 : 0) + l8;
                int bcol = ks * 16 + ((lg & 1) ? 8 : 0);
                uint32_t addr = (uint32_t)__cvta_generic_to_shared(Bt + brow * RSTR + bcol);
                uint32_t r0, r1, r2, r3;
                asm volatile("ldmatrix.sync.aligned.m8n8.x4.shared.b16 {%0,%1,%2,%3}, [%4];"
                             : "=r"(r0), "=r"(r1), "=r"(r2), "=r"(r3) : "r"(addr));
                bb[pp * 2 + 0][0] = r0; bb[pp * 2 + 0][1] = r1;
                bb[pp * 2 + 1][0] = r2; bb[pp * 2 + 1][1] = r3;
            }
#pragma unroll
            for (int mt = 0; mt < 4; ++mt)
#pragma unroll
                for (int nt = 0; nt < 4; ++nt)
                    asm volatile(
                        "mma.sync.aligned.m16n8k16.row.col.f32.f16.f16.f32 "
                        "{%0,%1,%2,%3},{%4,%5,%6,%7},{%8,%9},{%0,%1,%2,%3};\n"
                        : "+f"(acc[mt][nt][0]), "+f"(acc[mt][nt][1]),
                          "+f"(acc[mt][nt][2]), "+f"(acc[mt][nt][3])
                        : "r"(a[mt][0]), "r"(a[mt][1]), "r"(a[mt][2]), "r"(a[mt][3]),
                          "r"(bb[nt][0]), "r"(bb[nt][1]));
        }
    }
    cp_wait<0>();

    // Fused epilogue. feat recomputed from the fv components we already load:
    //   fv at base=(n*F+j)*3: [j,c0][j,c1][j,c2][j+1,c0][j+1,c1][j+1,c2]
#pragma unroll
    for (int mt = 0; mt < 4; ++mt) {
#pragma unroll
        for (int half = 0; half < 2; ++half) {
            int n = m0 + warpM + mt * 16 + r + half * 8;
            if (n >= N) continue;
#pragma unroll
            for (int nt = 0; nt < 4; ++nt) {
                int j = n0 + warpN + nt * 8 + 2 * c;
                float d0 = acc[mt][nt][half * 2 + 0];
                float d1 = acc[mt][nt][half * 2 + 1];
                size_t base = ((size_t)n * F + j) * 3;
                const float2* vp = reinterpret_cast<const float2*>(fv + base);
                float2 v0 = vp[0], v1 = vp[1], v2 = vp[2];
                float xa = v0.x + 1e-8f, ya = v0.y + 1e-8f, za = v1.x + 1e-8f;
                float xb = v1.y + 1e-8f, yb = v2.x + 1e-8f, zb = v2.y + 1e-8f;
                float ft0 = sqrtf(fmaf(xa, xa, fmaf(ya, ya, za * za)));
                float ft1 = sqrtf(fmaf(xb, xb, fmaf(yb, yb, zb * zb)));
                float gt0 = d0 + bias[j];
                float gt1 = d1 + bias[j + 1];
                float s0 = gt0 / (ft0 + zeta[j] + 1e-8f);
                float s1 = gt1 / (ft1 + zeta[j + 1] + 1e-8f);
                float2* op = reinterpret_cast<float2*>(out + base);
                float2 o0, o1, o2;
                o0.x = s0 * v0.x; o0.y = s0 * v0.y;
                o1.x = s0 * v1.x; o1.y = s1 * v1.y;
                o2.x = s1 * v2.x; o2.y = s1 * v2.y;
                op[0] = o0; op[1] = o1; op[2] = o2;
            }
        }
    }
}

// ---------------- launch -----------------------------------------------------
extern "C" void kernel_launch(void* const* d_in, const int* in_sizes, int n_in,
                              void* d_out, int out_size) {
    int o = (n_in >= 9) ? 3 : 2;
    const float* fv    = (const float*)d_in[0];
    const int*   seg   = (const int*)d_in[1];
    const float* alpha = (const float*)d_in[o];
    const float* beta  = (const float*)d_in[o + 1];
    const float* gamma = (const float*)d_in[o + 2];
    const float* zeta  = (const float*)d_in[o + 3];
    const float* W     = (const float*)d_in[o + 4];
    const float* bias  = (const float*)d_in[o + 5];
    int F = in_sizes[o];
    int N = in_sizes[0] / (3 * F);
    float* out = (float*)d_out;

    init_stats<<<(GMAX * FMAXD + 255) / 256, 256>>>(seg, N);

    int npb = 25;   // 25 | 1000: each block stays within one graph
    dim3 g1((F / 4 + 255) / 256, (N + npb - 1) / npb);
    pass1<<<g1, 256>>>(fv, seg, N, F, npb);

    dim3 g2(F / 256, GMAX);
    stats<<<g2, 256>>>(alpha, beta, gamma, F);

    long long yq = (long long)N * (F / 4);
    make_y<<<(unsigned)((yq + 255) / 256), 256>>>(seg, N, F);
    conv_w<<<(F * F / 4 + 255) / 256, 256>>>(W, F * F / 4);

    cudaFuncSetAttribute(gemm_fused, cudaFuncAttributeMaxDynamicSharedMemorySize, SMEM_B);
    dim3 gg(F / BN, (N + BM - 1) / BM);
    gemm_fused<<<gg, NTHR, SMEM_B>>>(fv, zeta, bias, out, N, F);
}

// round 13
// speedup vs baseline: 1.0798x; 1.0798x over previous
#include <cuda_runtime.h>
#include <cuda_fp16.h>
#include <cstdint>
#include <cstddef>

#define FMAXD 1024
#define GMAX  256
#define MAXN  40960

// ---------------- scratch (static device globals; no runtime allocation) ---
__device__ float  g_feat[(size_t)MAXN * FMAXD];
__device__ __half g_Yh[(size_t)MAXN * FMAXD];
__device__ __half g_Wh[(size_t)FMAXD * FMAXD];
__device__ float  g_sum[GMAX * FMAXD];
__device__ float  g_sq[GMAX * FMAXD];
__device__ float  g_s[GMAX * FMAXD];
__device__ float  g_t[GMAX * FMAXD];
__device__ int    g_cnt[GMAX];

// ---------------- helpers ---------------------------------------------------
__device__ __forceinline__ void cp16(uint32_t dst, const void* src) {
    asm volatile("cp.async.cg.shared.global [%0], [%1], 16;\n" :: "r"(dst), "l"(src));
}
__device__ __forceinline__ void cp_commit() { asm volatile("cp.async.commit_group;\n"); }
template <int n> __device__ __forceinline__ void cp_wait() {
    asm volatile("cp.async.wait_group %0;\n" :: "n"(n));
}
__device__ __forceinline__ void l2_prefetch(const void* p) {
    asm volatile("prefetch.global.L2 [%0];" :: "l"(p));
}
__device__ __forceinline__ void stcs2(float* p, float2 v) {
    asm volatile("st.global.cs.v2.f32 [%0], {%1, %2};" :: "l"(p), "f"(v.x), "f"(v.y));
}

// ---------------- small kernels ---------------------------------------------
__global__ void zero_stats() {
    int i = blockIdx.x * blockDim.x + threadIdx.x;
    if (i < GMAX * FMAXD) { g_sum[i] = 0.f; g_sq[i] = 0.f; }
    if (i < GMAX) g_cnt[i] = 0;
}

__global__ void count_nodes(const int* __restrict__ seg, int N) {
    __shared__ int h[GMAX];
    for (int i = threadIdx.x; i < GMAX; i += blockDim.x) h[i] = 0;
    __syncthreads();
    int i = blockIdx.x * blockDim.x + threadIdx.x;
    if (i < N) atomicAdd(&h[seg[i]], 1);
    __syncthreads();
    for (int i = threadIdx.x; i < GMAX; i += blockDim.x)
        if (h[i]) atomicAdd(&g_cnt[i], h[i]);
}

// Pass 1 (vectorized): each thread owns a feature-quad.
__global__ void pass1(const float* __restrict__ fv, const int* __restrict__ seg,
                      int N, int F, int npb) {
    int q  = blockIdx.x * blockDim.x + threadIdx.x;   // feature quad
    if (q >= F / 4) return;
    int n0 = blockIdx.y * npb;
    if (n0 >= N) return;
    int nend = min(n0 + npb, N);
    float s1[4] = {0.f, 0.f, 0.f, 0.f};
    float s2[4] = {0.f, 0.f, 0.f, 0.f};
    int curg = seg[n0];
    int f0 = 4 * q;
    for (int n = n0; n < nend; ++n) {
        int g = seg[n];
        if (g != curg) {
#pragma unroll
            for (int k = 0; k < 4; ++k) {
                atomicAdd(&g_sum[curg * F + f0 + k], s1[k]);
                atomicAdd(&g_sq[curg * F + f0 + k], s2[k]);
                s1[k] = 0.f; s2[k] = 0.f;
            }
            curg = g;
        }
        const float4* p = reinterpret_cast<const float4*>(fv + ((size_t)n * F + f0) * 3);
        float4 a = p[0], b = p[1], c = p[2];
        float x0 = a.x + 1e-8f, y0 = a.y + 1e-8f, z0 = a.z + 1e-8f;
        float x1 = a.w + 1e-8f, y1 = b.x + 1e-8f, z1 = b.y + 1e-8f;
        float x2 = b.z + 1e-8f, y2 = b.w + 1e-8f, z2 = c.x + 1e-8f;
        float x3 = c.y + 1e-8f, y3 = c.z + 1e-8f, z3 = c.w + 1e-8f;
        float4 ft;
        ft.x = sqrtf(fmaf(x0, x0, fmaf(y0, y0, z0 * z0)));
        ft.y = sqrtf(fmaf(x1, x1, fmaf(y1, y1, z1 * z1)));
        ft.z = sqrtf(fmaf(x2, x2, fmaf(y2, y2, z2 * z2)));
        ft.w = sqrtf(fmaf(x3, x3, fmaf(y3, y3, z3 * z3)));
        reinterpret_cast<float4*>(g_feat + (size_t)n * F + f0)[0] = ft;
        s1[0] += ft.x; s2[0] = fmaf(ft.x, ft.x, s2[0]);
        s1[1] += ft.y; s2[1] = fmaf(ft.y, ft.y, s2[1]);
        s1[2] += ft.z; s2[2] = fmaf(ft.z, ft.z, s2[2]);
        s1[3] += ft.w; s2[3] = fmaf(ft.w, ft.w, s2[3]);
    }
#pragma unroll
    for (int k = 0; k < 4; ++k) {
        atomicAdd(&g_sum[curg * F + f0 + k], s1[k]);
        atomicAdd(&g_sq[curg * F + f0 + k], s2[k]);
    }
}

// Per-(g,f) affine coefficients: y = feat*s + t
__global__ void stats(const float* __restrict__ alpha, const float* __restrict__ beta,
                      const float* __restrict__ gamma, int F) {
    int f = blockIdx.x * blockDim.x + threadIdx.x;
    int g = blockIdx.y;
    int c = g_cnt[g];
    if (c == 0) return;
    float invc = 1.f / (float)c;
    size_t idx = (size_t)g * F + f;
    float u  = g_sum[idx] * invc;
    float u2 = alpha[f] * u;
    float m2 = g_sq[idx] * invc;
    float sigma = m2 - 2.f * u2 * u + u2 * u2;
    float sn = sqrtf(sigma + 1e-6f);
    float iv = 1.f / (sn + 1e-6f);
    float sv = gamma[f] * iv;
    g_s[idx] = sv;
    g_t[idx] = fmaf(-u2, sv, beta[f]);
}

// Y = feat*s + t, cast to fp16. One block per node row, 128 thr x 8 elems:
// no div/mod, float4 loads, uint4 stores.
__global__ void make_y(const int* __restrict__ seg, int N, int F) {
    int n = blockIdx.x;
    int f0 = threadIdx.x * 8;
    int g = __ldg(&seg[n]);
    const float4* fp = reinterpret_cast<const float4*>(g_feat + (size_t)n * F + f0);
    const float4* sp = reinterpret_cast<const float4*>(g_s + (size_t)g * F + f0);
    const float4* tp = reinterpret_cast<const float4*>(g_t + (size_t)g * F + f0);
    float4 fa = fp[0], fb = fp[1];
    float4 sa = sp[0], sb = sp[1];
    float4 ta = tp[0], tb = tp[1];
    __half2 h[4];
    h[0].x = __float2half(fmaf(fa.x, sa.x, ta.x));
    h[0].y = __float2half(fmaf(fa.y, sa.y, ta.y));
    h[1].x = __float2half(fmaf(fa.z, sa.z, ta.z));
    h[1].y = __float2half(fmaf(fa.w, sa.w, ta.w));
    h[2].x = __float2half(fmaf(fb.x, sb.x, tb.x));
    h[2].y = __float2half(fmaf(fb.y, sb.y, tb.y));
    h[3].x = __float2half(fmaf(fb.z, sb.z, tb.z));
    h[3].y = __float2half(fmaf(fb.w, sb.w, tb.w));
    *reinterpret_cast<uint4*>(g_Yh + (size_t)n * F + f0) =
        *reinterpret_cast<const uint4*>(h);
}

__global__ void conv_w(const float* __restrict__ W, int total4) {
    int i = blockIdx.x * blockDim.x + threadIdx.x;
    if (i >= total4) return;
    float4 w = reinterpret_cast<const float4*>(W)[i];
    __half2 h01, h23;
    h01.x = __float2half(w.x); h01.y = __float2half(w.y);
    h23.x = __float2half(w.z); h23.y = __float2half(w.w);
    __half2* dst = reinterpret_cast<__half2*>(g_Wh + (size_t)4 * i);
    dst[0] = h01; dst[1] = h23;
}

// ---------------- fp16 mma.sync GEMM with fused final rescale epilogue ------
// BM=256, BN=128, 512 thr, warp tile 64x32, 4-stage single-sync pipeline.
// (Best-known config from R10.) Epilogue fv prefetch at kt==12 so the lines
// survive in L2 until the epilogue; out written with st.global.cs.
#define BM 256
#define BN 128
#define BK 64
#define RSTR 72                          // 64 data + 8 pad halfs (144B rows)
#define A_STG (BM * RSTR)
#define B_STG (BN * RSTR)
#define NSTAGE 4
#define SMEM_B ((NSTAGE * (A_STG + B_STG)) * 2)   // 221184 bytes
#define NTHR 512

__global__ void __launch_bounds__(NTHR, 1) gemm_fused(
    const float* __restrict__ fv, const float* __restrict__ zeta,
    const float* __restrict__ bias, float* __restrict__ out, int N, int F) {
    extern __shared__ __half sm[];
    __half* As = sm;
    __half* Bs = sm + NSTAGE * A_STG;
    int tid = threadIdx.x;
    int m0 = blockIdx.y * BM;
    int n0 = blockIdx.x * BN;
    uint32_t asBase = (uint32_t)__cvta_generic_to_shared(As);
    uint32_t bsBase = (uint32_t)__cvta_generic_to_shared(Bs);
    int NK = F / BK;                        // 16

    float acc[4][4][4];
#pragma unroll
    for (int a = 0; a < 4; ++a)
#pragma unroll
        for (int b = 0; b < 4; ++b)
#pragma unroll
            for (int c2 = 0; c2 < 4; ++c2) acc[a][b][c2] = 0.f;

    int wid = tid / 32, lane = tid % 32;
    int warpM = (wid >> 2) * 64;            // 4 warp rows (64 m each)
    int warpN = (wid & 3) * 32;             // 4 warp cols (32 n each)
    int r = lane >> 2, c = lane & 3;

    auto loadAB = [&](int st, int kt) {
#pragma unroll
        for (int it = 0; it < 4; ++it) {    // A: 2048 chunks / 512 thr
            int id = tid + NTHR * it;
            int row = id >> 3, ch = id & 7;
            int gr = m0 + row; if (gr > N - 1) gr = N - 1;
            const void* srcA = g_Yh + (size_t)gr * F + kt * BK + ch * 8;
            cp16(asBase + (uint32_t)(st * A_STG + row * RSTR) * 2u + ch * 16u, srcA);
        }
#pragma unroll
        for (int it = 0; it < 2; ++it) {    // B: 1024 chunks / 512 thr
            int id = tid + NTHR * it;
            int row = id >> 3, ch = id & 7;
            const void* srcB = g_Wh + (size_t)(n0 + row) * F + kt * BK + ch * 8;
            cp16(bsBase + (uint32_t)(st * B_STG + row * RSTR) * 2u + ch * 16u, srcB);
        }
    };

    // Prologue: NSTAGE-1 = 3 stages
    loadAB(0, 0); cp_commit();
    loadAB(1, 1); cp_commit();
    loadAB(2, 2); cp_commit();

    int l8 = lane & 7, lg = lane >> 3;      // ldmatrix lane grouping

    for (int kt = 0; kt < NK; ++kt) {
        int st = kt & 3;
        // committed = 3 + kt before this wait; wait_group 2 => tiles 0..kt done.
        cp_wait<2>();
        __syncthreads();
        // Issue tile kt+3 into stage (kt-1)&3 (consumed last iteration; all
        // warps past it once past this barrier). ONE sync per kt.
        {
            int kn = kt + NSTAGE - 1;
            if (kn < NK) loadAB(kn & 3, kn);
            cp_commit();                     // always commit (empty in tail)
        }
        if (kt == 12) {
            // L2-prefetch epilogue fv footprint LATE so it survives to the
            // epilogue: 256 rows x 128 feats x 12B = 3072 lines; 6/thread.
#pragma unroll
            for (int i = 0; i < 6; ++i) {
                int id = tid + NTHR * i;     // 0..3071
                int row = id / 12, sl = id % 12;
                int gr = m0 + row; if (gr > N - 1) gr = N - 1;
                const char* p = reinterpret_cast<const char*>(
                    fv + ((size_t)gr * F + n0) * 3) + sl * 128;
                l2_prefetch(p);
            }
        }
        const __half* At = As + st * A_STG;
        const __half* Bt = Bs + st * B_STG;
#pragma unroll
        for (int ks = 0; ks < 4; ++ks) {    // 4 k16-steps per BK=64
            uint32_t a[4][4], bb[4][2];
#pragma unroll
            for (int mt = 0; mt < 4; ++mt) {
                int arow = warpM + mt * 16 + ((lg & 1) ? 8 : 0) + l8;
                int acol = ks * 16 + ((lg >> 1) ? 8 : 0);
                uint32_t addr = (uint32_t)__cvta_generic_to_shared(At + arow * RSTR + acol);
                asm volatile("ldmatrix.sync.aligned.m8n8.x4.shared.b16 {%0,%1,%2,%3}, [%4];"
                             : "=r"(a[mt][0]), "=r"(a[mt][1]), "=r"(a[mt][2]), "=r"(a[mt][3])
                             : "r"(addr));
            }
#pragma unroll
            for (int pp = 0; pp < 2; ++pp) {
                int brow = warpN + pp * 16 + ((lg >> 1) ? 8 : 0) + l8;
                int bcol = ks * 16 + ((lg & 1) ? 8 : 0);
                uint32_t addr = (uint32_t)__cvta_generic_to_shared(Bt + brow * RSTR + bcol);
                uint32_t r0, r1, r2, r3;
                asm volatile("ldmatrix.sync.aligned.m8n8.x4.shared.b16 {%0,%1,%2,%3}, [%4];"
                             : "=r"(r0), "=r"(r1), "=r"(r2), "=r"(r3) : "r"(addr));
                bb[pp * 2 + 0][0] = r0; bb[pp * 2 + 0][1] = r1;
                bb[pp * 2 + 1][0] = r2; bb[pp * 2 + 1][1] = r3;
            }
#pragma unroll
            for (int mt = 0; mt < 4; ++mt)
#pragma unroll
                for (int nt = 0; nt < 4; ++nt)
                    asm volatile(
                        "mma.sync.aligned.m16n8k16.row.col.f32.f16.f16.f32 "
                        "{%0,%1,%2,%3},{%4,%5,%6,%7},{%8,%9},{%0,%1,%2,%3};\n"
                        : "+f"(acc[mt][nt][0]), "+f"(acc[mt][nt][1]),
                          "+f"(acc[mt][nt][2]), "+f"(acc[mt][nt][3])
                        : "r"(a[mt][0]), "r"(a[mt][1]), "r"(a[mt][2]), "r"(a[mt][3]),
                          "r"(bb[nt][0]), "r"(bb[nt][1]));
        }
    }
    cp_wait<0>();

    // Fused epilogue. feat recomputed from the fv components we already load;
    // out written with st.global.cs (streaming, never re-read).
#pragma unroll
    for (int mt = 0; mt < 4; ++mt) {
#pragma unroll
        for (int half = 0; half < 2; ++half) {
            int n = m0 + warpM + mt * 16 + r + half * 8;
            if (n >= N) continue;
#pragma unroll
            for (int nt = 0; nt < 4; ++nt) {
                int j = n0 + warpN + nt * 8 + 2 * c;
                float d0 = acc[mt][nt][half * 2 + 0];
                float d1 = acc[mt][nt][half * 2 + 1];
                size_t base = ((size_t)n * F + j) * 3;
                const float2* vp = reinterpret_cast<const float2*>(fv + base);
                float2 v0 = vp[0], v1 = vp[1], v2 = vp[2];
                float xa = v0.x + 1e-8f, ya = v0.y + 1e-8f, za = v1.x + 1e-8f;
                float xb = v1.y + 1e-8f, yb = v2.x + 1e-8f, zb = v2.y + 1e-8f;
                float ft0 = sqrtf(fmaf(xa, xa, fmaf(ya, ya, za * za)));
                float ft1 = sqrtf(fmaf(xb, xb, fmaf(yb, yb, zb * zb)));
                float gt0 = d0 + bias[j];
                float gt1 = d1 + bias[j + 1];
                float s0 = gt0 / (ft0 + zeta[j] + 1e-8f);
                float s1 = gt1 / (ft1 + zeta[j + 1] + 1e-8f);
                float* op = out + base;
                float2 o0, o1, o2;
                o0.x = s0 * v0.x; o0.y = s0 * v0.y;
                o1.x = s0 * v1.x; o1.y = s1 * v1.y;
                o2.x = s1 * v2.x; o2.y = s1 * v2.y;
                stcs2(op, o0); stcs2(op + 2, o1); stcs2(op + 4, o2);
            }
        }
    }
}

// ---------------- launch -----------------------------------------------------
extern "C" void kernel_launch(void* const* d_in, const int* in_sizes, int n_in,
                              void* d_out, int out_size) {
    int o = (n_in >= 9) ? 3 : 2;
    const float* fv    = (const float*)d_in[0];
    const int*   seg   = (const int*)d_in[1];
    const float* alpha = (const float*)d_in[o];
    const float* beta  = (const float*)d_in[o + 1];
    const float* gamma = (const float*)d_in[o + 2];
    const float* zeta  = (const float*)d_in[o + 3];
    const float* W     = (const float*)d_in[o + 4];
    const float* bias  = (const float*)d_in[o + 5];
    int F = in_sizes[o];
    int N = in_sizes[0] / (3 * F);
    float* out = (float*)d_out;

    zero_stats<<<(GMAX * FMAXD + 255) / 256, 256>>>();
    count_nodes<<<(N + 255) / 256, 256>>>(seg, N);

    int npb = 25;   // 25 | 1000: each block stays within one graph
    dim3 g1((F / 4 + 255) / 256, (N + npb - 1) / npb);
    pass1<<<g1, 256>>>(fv, seg, N, F, npb);

    dim3 g2(F / 256, GMAX);
    stats<<<g2, 256>>>(alpha, beta, gamma, F);

    make_y<<<N, F / 8>>>(seg, N, F);
    conv_w<<<(F * F / 4 + 255) / 256, 256>>>(W, F * F / 4);

    cudaFuncSetAttribute(gemm_fused, cudaFuncAttributeMaxDynamicSharedMemorySize, SMEM_B);
    dim3 gg(F / BN, (N + BM - 1) / BM);
    gemm_fused<<<gg, NTHR, SMEM_B>>>(fv, zeta, bias, out, N, F);
}

// round 14
// speedup vs baseline: 1.1101x; 1.0280x over previous
#include <cuda_runtime.h>
#include <cuda_fp16.h>
#include <cstdint>
#include <cstddef>

#define FMAXD 1024
#define GMAX  256
#define MAXN  40960

// ---------------- scratch (static device globals; no runtime allocation) ---
__device__ __half g_feath[(size_t)MAXN * FMAXD];   // feat (fp16; only make_y reads it)
__device__ __half g_Yh[(size_t)MAXN * FMAXD];
__device__ __half g_Wh[(size_t)FMAXD * FMAXD];
__device__ float  g_sum[GMAX * FMAXD];
__device__ float  g_sq[GMAX * FMAXD];
__device__ float  g_s[GMAX * FMAXD];
__device__ float  g_t[GMAX * FMAXD];
__device__ int    g_cnt[GMAX];

// ---------------- helpers ---------------------------------------------------
__device__ __forceinline__ void cp16(uint32_t dst, const void* src) {
    asm volatile("cp.async.cg.shared.global [%0], [%1], 16;\n" :: "r"(dst), "l"(src));
}
__device__ __forceinline__ void cp_commit() { asm volatile("cp.async.commit_group;\n"); }
template <int n> __device__ __forceinline__ void cp_wait() {
    asm volatile("cp.async.wait_group %0;\n" :: "n"(n));
}
__device__ __forceinline__ void l2_prefetch(const void* p) {
    asm volatile("prefetch.global.L2 [%0];" :: "l"(p));
}
__device__ __forceinline__ void stcs2(float* p, float2 v) {
    asm volatile("st.global.cs.v2.f32 [%0], {%1, %2};" :: "l"(p), "f"(v.x), "f"(v.y));
}

// ---------------- small kernels ---------------------------------------------
__global__ void zero_stats() {
    int i = blockIdx.x * blockDim.x + threadIdx.x;
    if (i < GMAX * FMAXD) { g_sum[i] = 0.f; g_sq[i] = 0.f; }
    if (i < GMAX) g_cnt[i] = 0;
}

__global__ void count_nodes(const int* __restrict__ seg, int N) {
    __shared__ int h[GMAX];
    for (int i = threadIdx.x; i < GMAX; i += blockDim.x) h[i] = 0;
    __syncthreads();
    int i = blockIdx.x * blockDim.x + threadIdx.x;
    if (i < N) atomicAdd(&h[seg[i]], 1);
    __syncthreads();
    for (int i = threadIdx.x; i < GMAX; i += blockDim.x)
        if (h[i]) atomicAdd(&g_cnt[i], h[i]);
}

// Pass 1 (vectorized): each thread owns a feature-quad. Sums in f32 (from
// pre-rounding values); feat stored fp16 (only make_y consumes it).
__global__ void pass1(const float* __restrict__ fv, const int* __restrict__ seg,
                      int N, int F, int npb) {
    int q  = blockIdx.x * blockDim.x + threadIdx.x;   // feature quad
    if (q >= F / 4) return;
    int n0 = blockIdx.y * npb;
    if (n0 >= N) return;
    int nend = min(n0 + npb, N);
    float s1[4] = {0.f, 0.f, 0.f, 0.f};
    float s2[4] = {0.f, 0.f, 0.f, 0.f};
    int curg = seg[n0];
    int f0 = 4 * q;
    for (int n = n0; n < nend; ++n) {
        int g = seg[n];
        if (g != curg) {
#pragma unroll
            for (int k = 0; k < 4; ++k) {
                atomicAdd(&g_sum[curg * F + f0 + k], s1[k]);
                atomicAdd(&g_sq[curg * F + f0 + k], s2[k]);
                s1[k] = 0.f; s2[k] = 0.f;
            }
            curg = g;
        }
        const float4* p = reinterpret_cast<const float4*>(fv + ((size_t)n * F + f0) * 3);
        float4 a = p[0], b = p[1], c = p[2];
        float x0 = a.x + 1e-8f, y0 = a.y + 1e-8f, z0 = a.z + 1e-8f;
        float x1 = a.w + 1e-8f, y1 = b.x + 1e-8f, z1 = b.y + 1e-8f;
        float x2 = b.z + 1e-8f, y2 = b.w + 1e-8f, z2 = c.x + 1e-8f;
        float x3 = c.y + 1e-8f, y3 = c.z + 1e-8f, z3 = c.w + 1e-8f;
        float4 ft;
        ft.x = sqrtf(fmaf(x0, x0, fmaf(y0, y0, z0 * z0)));
        ft.y = sqrtf(fmaf(x1, x1, fmaf(y1, y1, z1 * z1)));
        ft.z = sqrtf(fmaf(x2, x2, fmaf(y2, y2, z2 * z2)));
        ft.w = sqrtf(fmaf(x3, x3, fmaf(y3, y3, z3 * z3)));
        __half2 h01, h23;
        h01.x = __float2half(ft.x); h01.y = __float2half(ft.y);
        h23.x = __float2half(ft.z); h23.y = __float2half(ft.w);
        uint2 pk;
        pk.x = *reinterpret_cast<const uint32_t*>(&h01);
        pk.y = *reinterpret_cast<const uint32_t*>(&h23);
        *reinterpret_cast<uint2*>(g_feath + (size_t)n * F + f0) = pk;
        s1[0] += ft.x; s2[0] = fmaf(ft.x, ft.x, s2[0]);
        s1[1] += ft.y; s2[1] = fmaf(ft.y, ft.y, s2[1]);
        s1[2] += ft.z; s2[2] = fmaf(ft.z, ft.z, s2[2]);
        s1[3] += ft.w; s2[3] = fmaf(ft.w, ft.w, s2[3]);
    }
#pragma unroll
    for (int k = 0; k < 4; ++k) {
        atomicAdd(&g_sum[curg * F + f0 + k], s1[k]);
        atomicAdd(&g_sq[curg * F + f0 + k], s2[k]);
    }
}

// Per-(g,f) affine coefficients: y = feat*s + t
__global__ void stats(const float* __restrict__ alpha, const float* __restrict__ beta,
                      const float* __restrict__ gamma, int F) {
    int f = blockIdx.x * blockDim.x + threadIdx.x;
    int g = blockIdx.y;
    int c = g_cnt[g];
    if (c == 0) return;
    float invc = 1.f / (float)c;
    size_t idx = (size_t)g * F + f;
    float u  = g_sum[idx] * invc;
    float u2 = alpha[f] * u;
    float m2 = g_sq[idx] * invc;
    float sigma = m2 - 2.f * u2 * u + u2 * u2;
    float sn = sqrtf(sigma + 1e-6f);
    float iv = 1.f / (sn + 1e-6f);
    float sv = gamma[f] * iv;
    g_s[idx] = sv;
    g_t[idx] = fmaf(-u2, sv, beta[f]);
}

// Y = feat*s + t, cast to fp16. One block per node, 128 thr x 8 elems.
__global__ void make_y(const int* __restrict__ seg, int N, int F) {
    int n = blockIdx.x;
    int f0 = threadIdx.x * 8;
    int g = __ldg(&seg[n]);
    uint4 fpk = *reinterpret_cast<const uint4*>(g_feath + (size_t)n * F + f0);
    const __half2* fh = reinterpret_cast<const __half2*>(&fpk);
    const float4* sp = reinterpret_cast<const float4*>(g_s + (size_t)g * F + f0);
    const float4* tp = reinterpret_cast<const float4*>(g_t + (size_t)g * F + f0);
    float4 sa = sp[0], sb = sp[1];
    float4 ta = tp[0], tb = tp[1];
    float2 f0f = __half22float2(fh[0]), f1f = __half22float2(fh[1]);
    float2 f2f = __half22float2(fh[2]), f3f = __half22float2(fh[3]);
    __half2 h[4];
    h[0].x = __float2half(fmaf(f0f.x, sa.x, ta.x));
    h[0].y = __float2half(fmaf(f0f.y, sa.y, ta.y));
    h[1].x = __float2half(fmaf(f1f.x, sa.z, ta.z));
    h[1].y = __float2half(fmaf(f1f.y, sa.w, ta.w));
    h[2].x = __float2half(fmaf(f2f.x, sb.x, tb.x));
    h[2].y = __float2half(fmaf(f2f.y, sb.y, tb.y));
    h[3].x = __float2half(fmaf(f3f.x, sb.z, tb.z));
    h[3].y = __float2half(fmaf(f3f.y, sb.w, tb.w));
    *reinterpret_cast<uint4*>(g_Yh + (size_t)n * F + f0) =
        *reinterpret_cast<const uint4*>(h);
}

__global__ void conv_w(const float* __restrict__ W, int total4) {
    int i = blockIdx.x * blockDim.x + threadIdx.x;
    if (i >= total4) return;
    float4 w = reinterpret_cast<const float4*>(W)[i];
    __half2 h01, h23;
    h01.x = __float2half(w.x); h01.y = __float2half(w.y);
    h23.x = __float2half(w.z); h23.y = __float2half(w.w);
    __half2* dst = reinterpret_cast<__half2*>(g_Wh + (size_t)4 * i);
    dst[0] = h01; dst[1] = h23;
}

// ---------------- fp16 mma.sync GEMM with fused final rescale epilogue ------
// BM=256, BN=128, 512 thr, warp tile 64x32, 4-stage single-sync pipeline.
// Epilogue fv prefetch at kt==12; out written with st.global.cs.
#define BM 256
#define BN 128
#define BK 64
#define RSTR 72                          // 64 data + 8 pad halfs (144B rows)
#define A_STG (BM * RSTR)
#define B_STG (BN * RSTR)
#define NSTAGE 4
#define SMEM_B ((NSTAGE * (A_STG + B_STG)) * 2)   // 221184 bytes
#define NTHR 512

__global__ void __launch_bounds__(NTHR, 1) gemm_fused(
    const float* __restrict__ fv, const float* __restrict__ zeta,
    const float* __restrict__ bias, float* __restrict__ out, int N, int F) {
    extern __shared__ __half sm[];
    __half* As = sm;
    __half* Bs = sm + NSTAGE * A_STG;
    int tid = threadIdx.x;
    int m0 = blockIdx.y * BM;
    int n0 = blockIdx.x * BN;
    uint32_t asBase = (uint32_t)__cvta_generic_to_shared(As);
    uint32_t bsBase = (uint32_t)__cvta_generic_to_shared(Bs);
    int NK = F / BK;                        // 16

    float acc[4][4][4];
#pragma unroll
    for (int a = 0; a < 4; ++a)
#pragma unroll
        for (int b = 0; b < 4; ++b)
#pragma unroll
            for (int c2 = 0; c2 < 4; ++c2) acc[a][b][c2] = 0.f;

    int wid = tid / 32, lane = tid % 32;
    int warpM = (wid >> 2) * 64;            // 4 warp rows (64 m each)
    int warpN = (wid & 3) * 32;             // 4 warp cols (32 n each)
    int r = lane >> 2, c = lane & 3;

    auto loadAB = [&](int st, int kt) {
#pragma unroll
        for (int it = 0; it < 4; ++it) {    // A: 2048 chunks / 512 thr
            int id = tid + NTHR * it;
            int row = id >> 3, ch = id & 7;
            int gr = m0 + row; if (gr > N - 1) gr = N - 1;
            const void* srcA = g_Yh + (size_t)gr * F + kt * BK + ch * 8;
            cp16(asBase + (uint32_t)(st * A_STG + row * RSTR) * 2u + ch * 16u, srcA);
        }
#pragma unroll
        for (int it = 0; it < 2; ++it) {    // B: 1024 chunks / 512 thr
            int id = tid + NTHR * it;
            int row = id >> 3, ch = id & 7;
            const void* srcB = g_Wh + (size_t)(n0 + row) * F + kt * BK + ch * 8;
            cp16(bsBase + (uint32_t)(st * B_STG + row * RSTR) * 2u + ch * 16u, srcB);
        }
    };

    // Prologue: NSTAGE-1 = 3 stages
    loadAB(0, 0); cp_commit();
    loadAB(1, 1); cp_commit();
    loadAB(2, 2); cp_commit();

    int l8 = lane & 7, lg = lane >> 3;      // ldmatrix lane grouping

    for (int kt = 0; kt < NK; ++kt) {
        int st = kt & 3;
        // committed = 3 + kt before this wait; wait_group 2 => tiles 0..kt done.
        cp_wait<2>();
        __syncthreads();
        // Issue tile kt+3 into stage (kt-1)&3 (consumed last iteration).
        {
            int kn = kt + NSTAGE - 1;
            if (kn < NK) loadAB(kn & 3, kn);
            cp_commit();                     // always commit (empty in tail)
        }
        if (kt == 12) {
            // L2-prefetch epilogue fv footprint LATE so it survives:
            // 256 rows x 128 feats x 12B = 3072 lines; 6/thread.
#pragma unroll
            for (int i = 0; i < 6; ++i) {
                int id = tid + NTHR * i;     // 0..3071
                int row = id / 12, sl = id % 12;
                int gr = m0 + row; if (gr > N - 1) gr = N - 1;
                const char* p = reinterpret_cast<const char*>(
                    fv + ((size_t)gr * F + n0) * 3) + sl * 128;
                l2_prefetch(p);
            }
        }
        const __half* At = As + st * A_STG;
        const __half* Bt = Bs + st * B_STG;
#pragma unroll
        for (int ks = 0; ks < 4; ++ks) {    // 4 k16-steps per BK=64
            uint32_t a[4][4], bb[4][2];
#pragma unroll
            for (int mt = 0; mt < 4; ++mt) {
                int arow = warpM + mt * 16 + ((lg & 1) ? 8 : 0) + l8;
                int acol = ks * 16 + ((lg >> 1) ? 8 : 0);
                uint32_t addr = (uint32_t)__cvta_generic_to_shared(At + arow * RSTR + acol);
                asm volatile("ldmatrix.sync.aligned.m8n8.x4.shared.b16 {%0,%1,%2,%3}, [%4];"
                             : "=r"(a[mt][0]), "=r"(a[mt][1]), "=r"(a[mt][2]), "=r"(a[mt][3])
                             : "r"(addr));
            }
#pragma unroll
            for (int pp = 0; pp < 2; ++pp) {
                int brow = warpN + pp * 16 + ((lg >> 1) ? 8 : 0) + l8;
                int bcol = ks * 16 + ((lg & 1) ? 8 : 0);
                uint32_t addr = (uint32_t)__cvta_generic_to_shared(Bt + brow * RSTR + bcol);
                uint32_t r0, r1, r2, r3;
                asm volatile("ldmatrix.sync.aligned.m8n8.x4.shared.b16 {%0,%1,%2,%3}, [%4];"
                             : "=r"(r0), "=r"(r1), "=r"(r2), "=r"(r3) : "r"(addr));
                bb[pp * 2 + 0][0] = r0; bb[pp * 2 + 0][1] = r1;
                bb[pp * 2 + 1][0] = r2; bb[pp * 2 + 1][1] = r3;
            }
#pragma unroll
            for (int mt = 0; mt < 4; ++mt)
#pragma unroll
                for (int nt = 0; nt < 4; ++nt)
                    asm volatile(
                        "mma.sync.aligned.m16n8k16.row.col.f32.f16.f16.f32 "
                        "{%0,%1,%2,%3},{%4,%5,%6,%7},{%8,%9},{%0,%1,%2,%3};\n"
                        : "+f"(acc[mt][nt][0]), "+f"(acc[mt][nt][1]),
                          "+f"(acc[mt][nt][2]), "+f"(acc[mt][nt][3])
                        : "r"(a[mt][0]), "r"(a[mt][1]), "r"(a[mt][2]), "r"(a[mt][3]),
                          "r"(bb[nt][0]), "r"(bb[nt][1]));
        }
    }
    cp_wait<0>();

    // Fused epilogue. feat recomputed (f32) from the fv components we load;
    // out written with st.global.cs (streaming, never re-read).
#pragma unroll
    for (int mt = 0; mt < 4; ++mt) {
#pragma unroll
        for (int half = 0; half < 2; ++half) {
            int n = m0 + warpM + mt * 16 + r + half * 8;
            if (n >= N) continue;
#pragma unroll
            for (int nt = 0; nt < 4; ++nt) {
                int j = n0 + warpN + nt * 8 + 2 * c;
                float d0 = acc[mt][nt][half * 2 + 0];
                float d1 = acc[mt][nt][half * 2 + 1];
                size_t base = ((size_t)n * F + j) * 3;
                const float2* vp = reinterpret_cast<const float2*>(fv + base);
                float2 v0 = vp[0], v1 = vp[1], v2 = vp[2];
                float xa = v0.x + 1e-8f, ya = v0.y + 1e-8f, za = v1.x + 1e-8f;
                float xb = v1.y + 1e-8f, yb = v2.x + 1e-8f, zb = v2.y + 1e-8f;
                float ft0 = sqrtf(fmaf(xa, xa, fmaf(ya, ya, za * za)));
                float ft1 = sqrtf(fmaf(xb, xb, fmaf(yb, yb, zb * zb)));
                float gt0 = d0 + bias[j];
                float gt1 = d1 + bias[j + 1];
                float s0 = gt0 / (ft0 + zeta[j] + 1e-8f);
                float s1 = gt1 / (ft1 + zeta[j + 1] + 1e-8f);
                float* op = out + base;
                float2 o0, o1, o2;
                o0.x = s0 * v0.x; o0.y = s0 * v0.y;
                o1.x = s0 * v1.x; o1.y = s1 * v1.y;
                o2.x = s1 * v2.x; o2.y = s1 * v2.y;
                stcs2(op, o0); stcs2(op + 2, o1); stcs2(op + 4, o2);
            }
        }
    }
}

// ---------------- launch -----------------------------------------------------
extern "C" void kernel_launch(void* const* d_in, const int* in_sizes, int n_in,
                              void* d_out, int out_size) {
    int o = (n_in >= 9) ? 3 : 2;
    const float* fv    = (const float*)d_in[0];
    const int*   seg   = (const int*)d_in[1];
    const float* alpha = (const float*)d_in[o];
    const float* beta  = (const float*)d_in[o + 1];
    const float* gamma = (const float*)d_in[o + 2];
    const float* zeta  = (const float*)d_in[o + 3];
    const float* W     = (const float*)d_in[o + 4];
    const float* bias  = (const float*)d_in[o + 5];
    int F = in_sizes[o];
    int N = in_sizes[0] / (3 * F);
    float* out = (float*)d_out;

    zero_stats<<<(GMAX * FMAXD + 255) / 256, 256>>>();
    count_nodes<<<(N + 255) / 256, 256>>>(seg, N);

    int npb = 20;   // 20 | 1000: each block stays within one graph
    dim3 g1((F / 4 + 255) / 256, (N + npb - 1) / npb);
    pass1<<<g1, 256>>>(fv, seg, N, F, npb);

    dim3 g2(F / 256, GMAX);
    stats<<<g2, 256>>>(alpha, beta, gamma, F);

    make_y<<<N, F / 8>>>(seg, N, F);
    conv_w<<<(F * F / 4 + 255) / 256, 256>>>(W, F * F / 4);

    cudaFuncSetAttribute(gemm_fused, cudaFuncAttributeMaxDynamicSharedMemorySize, SMEM_B);
    dim3 gg(F / BN, (N + BM - 1) / BM);
    gemm_fused<<<gg, NTHR, SMEM_B>>>(fv, zeta, bias, out, N, F);
}

// round 15
// speedup vs baseline: 1.1719x; 1.0557x over previous
#include <cuda_runtime.h>
#include <cuda_fp16.h>
#include <cstdint>
#include <cstddef>

#define FMAXD 1024
#define GMAX  256
#define MAXN  40960

// ---------------- scratch (static device globals; no runtime allocation) ---
__device__ __half g_feath[(size_t)MAXN * FMAXD];   // feat (fp16; only make_y reads it)
__device__ __half g_Yh[(size_t)MAXN * FMAXD];
__device__ __half g_Wh[(size_t)FMAXD * FMAXD];
__device__ float  g_sum[GMAX * FMAXD];
__device__ float  g_sq[GMAX * FMAXD];
__device__ float  g_s[GMAX * FMAXD];
__device__ float  g_t[GMAX * FMAXD];
__device__ int    g_cnt[GMAX];

// ---------------- helpers ---------------------------------------------------
__device__ __forceinline__ void cp16(uint32_t dst, const void* src) {
    asm volatile("cp.async.cg.shared.global [%0], [%1], 16;\n" :: "r"(dst), "l"(src));
}
__device__ __forceinline__ void cp_commit() { asm volatile("cp.async.commit_group;\n"); }
template <int n> __device__ __forceinline__ void cp_wait() {
    asm volatile("cp.async.wait_group %0;\n" :: "n"(n));
}
__device__ __forceinline__ void l2_prefetch(const void* p) {
    asm volatile("prefetch.global.L2 [%0];" :: "l"(p));
}
__device__ __forceinline__ void stcs2(float* p, float2 v) {
    asm volatile("st.global.cs.v2.f32 [%0], {%1, %2};" :: "l"(p), "f"(v.x), "f"(v.y));
}

// ---------------- small kernels ---------------------------------------------
__global__ void zero_stats() {
    int i = blockIdx.x * blockDim.x + threadIdx.x;
    if (i < GMAX * FMAXD) { g_sum[i] = 0.f; g_sq[i] = 0.f; }
    if (i < GMAX) g_cnt[i] = 0;
}

__global__ void count_nodes(const int* __restrict__ seg, int N) {
    __shared__ int h[GMAX];
    for (int i = threadIdx.x; i < GMAX; i += blockDim.x) h[i] = 0;
    __syncthreads();
    int i = blockIdx.x * blockDim.x + threadIdx.x;
    if (i < N) atomicAdd(&h[seg[i]], 1);
    __syncthreads();
    for (int i = threadIdx.x; i < GMAX; i += blockDim.x)
        if (h[i]) atomicAdd(&g_cnt[i], h[i]);
}

// Pass 1 (vectorized): each thread owns a feature-quad. Sums in f32 (from
// pre-rounding values); feat stored fp16 (only make_y consumes it).
__global__ void pass1(const float* __restrict__ fv, const int* __restrict__ seg,
                      int N, int F, int npb) {
    int q  = blockIdx.x * blockDim.x + threadIdx.x;   // feature quad
    if (q >= F / 4) return;
    int n0 = blockIdx.y * npb;
    if (n0 >= N) return;
    int nend = min(n0 + npb, N);
    float s1[4] = {0.f, 0.f, 0.f, 0.f};
    float s2[4] = {0.f, 0.f, 0.f, 0.f};
    int curg = seg[n0];
    int f0 = 4 * q;
    for (int n = n0; n < nend; ++n) {
        int g = seg[n];
        if (g != curg) {
#pragma unroll
            for (int k = 0; k < 4; ++k) {
                atomicAdd(&g_sum[curg * F + f0 + k], s1[k]);
                atomicAdd(&g_sq[curg * F + f0 + k], s2[k]);
                s1[k] = 0.f; s2[k] = 0.f;
            }
            curg = g;
        }
        const float4* p = reinterpret_cast<const float4*>(fv + ((size_t)n * F + f0) * 3);
        float4 a = p[0], b = p[1], c = p[2];
        float x0 = a.x + 1e-8f, y0 = a.y + 1e-8f, z0 = a.z + 1e-8f;
        float x1 = a.w + 1e-8f, y1 = b.x + 1e-8f, z1 = b.y + 1e-8f;
        float x2 = b.z + 1e-8f, y2 = b.w + 1e-8f, z2 = c.x + 1e-8f;
        float x3 = c.y + 1e-8f, y3 = c.z + 1e-8f, z3 = c.w + 1e-8f;
        float4 ft;
        ft.x = sqrtf(fmaf(x0, x0, fmaf(y0, y0, z0 * z0)));
        ft.y = sqrtf(fmaf(x1, x1, fmaf(y1, y1, z1 * z1)));
        ft.z = sqrtf(fmaf(x2, x2, fmaf(y2, y2, z2 * z2)));
        ft.w = sqrtf(fmaf(x3, x3, fmaf(y3, y3, z3 * z3)));
        __half2 h01, h23;
        h01.x = __float2half(ft.x); h01.y = __float2half(ft.y);
        h23.x = __float2half(ft.z); h23.y = __float2half(ft.w);
        uint2 pk;
        pk.x = *reinterpret_cast<const uint32_t*>(&h01);
        pk.y = *reinterpret_cast<const uint32_t*>(&h23);
        *reinterpret_cast<uint2*>(g_feath + (size_t)n * F + f0) = pk;
        s1[0] += ft.x; s2[0] = fmaf(ft.x, ft.x, s2[0]);
        s1[1] += ft.y; s2[1] = fmaf(ft.y, ft.y, s2[1]);
        s1[2] += ft.z; s2[2] = fmaf(ft.z, ft.z, s2[2]);
        s1[3] += ft.w; s2[3] = fmaf(ft.w, ft.w, s2[3]);
    }
#pragma unroll
    for (int k = 0; k < 4; ++k) {
        atomicAdd(&g_sum[curg * F + f0 + k], s1[k]);
        atomicAdd(&g_sq[curg * F + f0 + k], s2[k]);
    }
}

// Per-(g,f) affine coefficients: y = feat*s + t
__global__ void stats(const float* __restrict__ alpha, const float* __restrict__ beta,
                      const float* __restrict__ gamma, int F) {
    int f = blockIdx.x * blockDim.x + threadIdx.x;
    int g = blockIdx.y;
    int c = g_cnt[g];
    if (c == 0) return;
    float invc = 1.f / (float)c;
    size_t idx = (size_t)g * F + f;
    float u  = g_sum[idx] * invc;
    float u2 = alpha[f] * u;
    float m2 = g_sq[idx] * invc;
    float sigma = m2 - 2.f * u2 * u + u2 * u2;
    float sn = sqrtf(sigma + 1e-6f);
    float iv = 1.f / (sn + 1e-6f);
    float sv = gamma[f] * iv;
    g_s[idx] = sv;
    g_t[idx] = fmaf(-u2, sv, beta[f]);
}

// Y = feat*s + t, cast to fp16. One block per node, 128 thr x 8 elems.
__global__ void make_y(const int* __restrict__ seg, int N, int F) {
    int n = blockIdx.x;
    int f0 = threadIdx.x * 8;
    int g = __ldg(&seg[n]);
    uint4 fpk = *reinterpret_cast<const uint4*>(g_feath + (size_t)n * F + f0);
    const __half2* fh = reinterpret_cast<const __half2*>(&fpk);
    const float4* sp = reinterpret_cast<const float4*>(g_s + (size_t)g * F + f0);
    const float4* tp = reinterpret_cast<const float4*>(g_t + (size_t)g * F + f0);
    float4 sa = sp[0], sb = sp[1];
    float4 ta = tp[0], tb = tp[1];
    float2 f0f = __half22float2(fh[0]), f1f = __half22float2(fh[1]);
    float2 f2f = __half22float2(fh[2]), f3f = __half22float2(fh[3]);
    __half2 h[4];
    h[0].x = __float2half(fmaf(f0f.x, sa.x, ta.x));
    h[0].y = __float2half(fmaf(f0f.y, sa.y, ta.y));
    h[1].x = __float2half(fmaf(f1f.x, sa.z, ta.z));
    h[1].y = __float2half(fmaf(f1f.y, sa.w, ta.w));
    h[2].x = __float2half(fmaf(f2f.x, sb.x, tb.x));
    h[2].y = __float2half(fmaf(f2f.y, sb.y, tb.y));
    h[3].x = __float2half(fmaf(f3f.x, sb.z, tb.z));
    h[3].y = __float2half(fmaf(f3f.y, sb.w, tb.w));
    *reinterpret_cast<uint4*>(g_Yh + (size_t)n * F + f0) =
        *reinterpret_cast<const uint4*>(h);
}

__global__ void conv_w(const float* __restrict__ W, int total4) {
    int i = blockIdx.x * blockDim.x + threadIdx.x;
    if (i >= total4) return;
    float4 w = reinterpret_cast<const float4*>(W)[i];
    __half2 h01, h23;
    h01.x = __float2half(w.x); h01.y = __float2half(w.y);
    h23.x = __float2half(w.z); h23.y = __float2half(w.w);
    __half2* dst = reinterpret_cast<__half2*>(g_Wh + (size_t)4 * i);
    dst[0] = h01; dst[1] = h23;
}

// ---------------- fp16 mma.sync GEMM with fused final rescale epilogue ------
// BM=128, BN=128, 256 thr, warp tile 64x32, NSTAGE=3, occ 2: co-resident CTA
// overlaps epilogue DRAM with the other CTA's HMMA mainloop. Late fv prefetch
// + streaming out stores (from R13/R14).
#define BM 128
#define BN 128
#define BK 64
#define RSTR 72                          // 64 data + 8 pad halfs (144B rows)
#define A_STG (BM * RSTR)
#define B_STG (BN * RSTR)
#define NSTAGE 3
#define SMEM_B ((NSTAGE * (A_STG + B_STG)) * 2)   // 110592 bytes
#define NTHR 256

__global__ void __launch_bounds__(NTHR, 2) gemm_fused(
    const float* __restrict__ fv, const float* __restrict__ zeta,
    const float* __restrict__ bias, float* __restrict__ out, int N, int F) {
    extern __shared__ __half sm[];
    __half* As = sm;
    __half* Bs = sm + NSTAGE * A_STG;
    int tid = threadIdx.x;
    int m0 = blockIdx.y * BM;
    int n0 = blockIdx.x * BN;
    uint32_t asBase = (uint32_t)__cvta_generic_to_shared(As);
    uint32_t bsBase = (uint32_t)__cvta_generic_to_shared(Bs);
    int NK = F / BK;                        // 16

    float acc[4][4][4];
#pragma unroll
    for (int a = 0; a < 4; ++a)
#pragma unroll
        for (int b = 0; b < 4; ++b)
#pragma unroll
            for (int c2 = 0; c2 < 4; ++c2) acc[a][b][c2] = 0.f;

    int wid = tid / 32, lane = tid % 32;
    int warpM = (wid >> 2) * 64;            // 2 warp rows (64 m each)
    int warpN = (wid & 3) * 32;             // 4 warp cols (32 n each)
    int r = lane >> 2, c = lane & 3;

    auto loadAB = [&](int st, int kt) {
#pragma unroll
        for (int it = 0; it < 4; ++it) {    // A: 1024 chunks / 256 thr
            int id = tid + NTHR * it;
            int row = id >> 3, ch = id & 7;
            int gr = m0 + row; if (gr > N - 1) gr = N - 1;
            const void* srcA = g_Yh + (size_t)gr * F + kt * BK + ch * 8;
            cp16(asBase + (uint32_t)(st * A_STG + row * RSTR) * 2u + ch * 16u, srcA);
        }
#pragma unroll
        for (int it = 0; it < 4; ++it) {    // B: 1024 chunks / 256 thr
            int id = tid + NTHR * it;
            int row = id >> 3, ch = id & 7;
            const void* srcB = g_Wh + (size_t)(n0 + row) * F + kt * BK + ch * 8;
            cp16(bsBase + (uint32_t)(st * B_STG + row * RSTR) * 2u + ch * 16u, srcB);
        }
    };

    // Prologue: NSTAGE-1 = 2 stages
    loadAB(0, 0); cp_commit();
    loadAB(1, 1); cp_commit();

    int l8 = lane & 7, lg = lane >> 3;      // ldmatrix lane grouping

    for (int kt = 0; kt < NK; ++kt) {
        int st = kt % NSTAGE;
        // committed = 2 + kt before this wait; wait_group 1 => tiles 0..kt done.
        cp_wait<1>();
        __syncthreads();
        // Issue tile kt+2 into stage (kt+2)%3 = (kt-1)%3, consumed last
        // iteration; all warps past it once past this barrier. 1 sync/kt.
        {
            int kn = kt + NSTAGE - 1;
            if (kn < NK) loadAB(kn % NSTAGE, kn);
            cp_commit();                     // always commit (empty in tail)
        }
        if (kt == 12) {
            // L2-prefetch epilogue fv footprint LATE so it survives:
            // 128 rows x 128 feats x 12B = 1536 lines; 6/thread.
#pragma unroll
            for (int i = 0; i < 6; ++i) {
                int id = tid + NTHR * i;     // 0..1535
                int row = id / 12, sl = id % 12;
                int gr = m0 + row; if (gr > N - 1) gr = N - 1;
                const char* p = reinterpret_cast<const char*>(
                    fv + ((size_t)gr * F + n0) * 3) + sl * 128;
                l2_prefetch(p);
            }
        }
        const __half* At = As + st * A_STG;
        const __half* Bt = Bs + st * B_STG;
#pragma unroll
        for (int ks = 0; ks < 4; ++ks) {    // 4 k16-steps per BK=64
            uint32_t a[4][4], bb[4][2];
#pragma unroll
            for (int mt = 0; mt < 4; ++mt) {
                int arow = warpM + mt * 16 + ((lg & 1) ? 8 : 0) + l8;
                int acol = ks * 16 + ((lg >> 1) ? 8 : 0);
                uint32_t addr = (uint32_t)__cvta_generic_to_shared(At + arow * RSTR + acol);
                asm volatile("ldmatrix.sync.aligned.m8n8.x4.shared.b16 {%0,%1,%2,%3}, [%4];"
                             : "=r"(a[mt][0]), "=r"(a[mt][1]), "=r"(a[mt][2]), "=r"(a[mt][3])
                             : "r"(addr));
            }
#pragma unroll
            for (int pp = 0; pp < 2; ++pp) {
                int brow = warpN + pp * 16 + ((lg >> 1) ? 8 : 0) + l8;
                int bcol = ks * 16 + ((lg & 1) ? 8 : 0);
                uint32_t addr = (uint32_t)__cvta_generic_to_shared(Bt + brow * RSTR + bcol);
                uint32_t r0, r1, r2, r3;
                asm volatile("ldmatrix.sync.aligned.m8n8.x4.shared.b16 {%0,%1,%2,%3}, [%4];"
                             : "=r"(r0), "=r"(r1), "=r"(r2), "=r"(r3) : "r"(addr));
                bb[pp * 2 + 0][0] = r0; bb[pp * 2 + 0][1] = r1;
                bb[pp * 2 + 1][0] = r2; bb[pp * 2 + 1][1] = r3;
            }
#pragma unroll
            for (int mt = 0; mt < 4; ++mt)
#pragma unroll
                for (int nt = 0; nt < 4; ++nt)
                    asm volatile(
                        "mma.sync.aligned.m16n8k16.row.col.f32.f16.f16.f32 "
                        "{%0,%1,%2,%3},{%4,%5,%6,%7},{%8,%9},{%0,%1,%2,%3};\n"
                        : "+f"(acc[mt][nt][0]), "+f"(acc[mt][nt][1]),
                          "+f"(acc[mt][nt][2]), "+f"(acc[mt][nt][3])
                        : "r"(a[mt][0]), "r"(a[mt][1]), "r"(a[mt][2]), "r"(a[mt][3]),
                          "r"(bb[nt][0]), "r"(bb[nt][1]));
        }
    }
    cp_wait<0>();

    // Fused epilogue. feat recomputed (f32) from the fv components we load;
    // out written with st.global.cs (streaming, never re-read).
#pragma unroll
    for (int mt = 0; mt < 4; ++mt) {
#pragma unroll
        for (int half = 0; half < 2; ++half) {
            int n = m0 + warpM + mt * 16 + r + half * 8;
            if (n >= N) continue;
#pragma unroll
            for (int nt = 0; nt < 4; ++nt) {
                int j = n0 + warpN + nt * 8 + 2 * c;
                float d0 = acc[mt][nt][half * 2 + 0];
                float d1 = acc[mt][nt][half * 2 + 1];
                size_t base = ((size_t)n * F + j) * 3;
                const float2* vp = reinterpret_cast<const float2*>(fv + base);
                float2 v0 = vp[0], v1 = vp[1], v2 = vp[2];
                float xa = v0.x + 1e-8f, ya = v0.y + 1e-8f, za = v1.x + 1e-8f;
                float xb = v1.y + 1e-8f, yb = v2.x + 1e-8f, zb = v2.y + 1e-8f;
                float ft0 = sqrtf(fmaf(xa, xa, fmaf(ya, ya, za * za)));
                float ft1 = sqrtf(fmaf(xb, xb, fmaf(yb, yb, zb * zb)));
                float gt0 = d0 + bias[j];
                float gt1 = d1 + bias[j + 1];
                float s0 = gt0 / (ft0 + zeta[j] + 1e-8f);
                float s1 = gt1 / (ft1 + zeta[j + 1] + 1e-8f);
                float* op = out + base;
                float2 o0, o1, o2;
                o0.x = s0 * v0.x; o0.y = s0 * v0.y;
                o1.x = s0 * v1.x; o1.y = s1 * v1.y;
                o2.x = s1 * v2.x; o2.y = s1 * v2.y;
                stcs2(op, o0); stcs2(op + 2, o1); stcs2(op + 4, o2);
            }
        }
    }
}

// ---------------- launch -----------------------------------------------------
extern "C" void kernel_launch(void* const* d_in, const int* in_sizes, int n_in,
                              void* d_out, int out_size) {
    int o = (n_in >= 9) ? 3 : 2;
    const float* fv    = (const float*)d_in[0];
    const int*   seg   = (const int*)d_in[1];
    const float* alpha = (const float*)d_in[o];
    const float* beta  = (const float*)d_in[o + 1];
    const float* gamma = (const float*)d_in[o + 2];
    const float* zeta  = (const float*)d_in[o + 3];
    const float* W     = (const float*)d_in[o + 4];
    const float* bias  = (const float*)d_in[o + 5];
    int F = in_sizes[o];
    int N = in_sizes[0] / (3 * F);
    float* out = (float*)d_out;

    zero_stats<<<(GMAX * FMAXD + 255) / 256, 256>>>();
    count_nodes<<<(N + 255) / 256, 256>>>(seg, N);

    int npb = 20;   // 20 | 1000: each block stays within one graph
    dim3 g1((F / 4 + 255) / 256, (N + npb - 1) / npb);
    pass1<<<g1, 256>>>(fv, seg, N, F, npb);

    dim3 g2(F / 256, GMAX);
    stats<<<g2, 256>>>(alpha, beta, gamma, F);

    make_y<<<N, F / 8>>>(seg, N, F);
    conv_w<<<(F * F / 4 + 255) / 256, 256>>>(W, F * F / 4);

    cudaFuncSetAttribute(gemm_fused, cudaFuncAttributeMaxDynamicSharedMemorySize, SMEM_B);
    dim3 gg(F / BN, (N + BM - 1) / BM);
    gemm_fused<<<gg, NTHR, SMEM_B>>>(fv, zeta, bias, out, N, F);
}